// round 2
// baseline (speedup 1.0000x reference)
#include <cuda_runtime.h>
#include <cuda_bf16.h>

// Problem constants (fixed by the dataset)
#define NN 100000
#define EE 1600000
#define FF 128
#define NC 40

// Scratch buffers: 3 x [N,128] fp32 = 3 x 51.2MB (device globals; no allocation)
__device__ float g_bufA[NN * FF];
__device__ float g_bufB[NN * FF];
__device__ float g_bufC[NN * FF];

// ---------------------------------------------------------------------------
// out[i] = (1 + *eps) * in[i]   (vectorized float4)
// ---------------------------------------------------------------------------
__global__ void scale_copy(const float4* __restrict__ in, const float* __restrict__ eps,
                           float4* __restrict__ out, int n4) {
    int i = blockIdx.x * blockDim.x + threadIdx.x;
    if (i < n4) {
        float s = 1.0f + *eps;
        float4 v = in[i];
        v.x *= s; v.y *= s; v.z *= s; v.w *= s;
        out[i] = v;
    }
}

// ---------------------------------------------------------------------------
// Edge kernel: for each edge e: aggr[dst[e]] += relu(x[src[e]] + ea[e]*We + be)
// Warp-per-edge. Each lane owns 4 features (float4). Indices staged 32 edges
// per warp iteration and broadcast via shfl. Scatter uses red.global.add.v4.f32.
// edge_index is int32 (JAX x64 disabled: jnp.int64 request silently -> int32).
// ---------------------------------------------------------------------------
__global__ void __launch_bounds__(256) edge_msg(
    const float4* __restrict__ x,           // [N, 32] float4 view of [N,128]
    const int* __restrict__ ei,             // [2, E] int32
    const float* __restrict__ ea,           // [E]
    const float* __restrict__ We,           // [128]
    const float* __restrict__ be,           // [128]
    float* __restrict__ aggr,               // [N, 128]
    int E)
{
    const int lane = threadIdx.x & 31;
    const int warp_global = (blockIdx.x * blockDim.x + threadIdx.x) >> 5;
    const int warp_stride = (gridDim.x * blockDim.x) >> 5;
    const int nchunk = (E + 31) / 32;

    const float4 we4 = ((const float4*)We)[lane];
    const float4 be4 = ((const float4*)be)[lane];

    for (int chunk = warp_global; chunk < nchunk; chunk += warp_stride) {
        int e = chunk * 32 + lane;
        int s = 0, d = 0;
        float a = 0.0f;
        if (e < E) {
            s = ei[e];
            d = ei[E + e];
            a = ea[e];
        }
        int cnt = E - chunk * 32;
        if (cnt > 32) cnt = 32;
        for (int j = 0; j < cnt; j++) {
            int sj = __shfl_sync(0xffffffffu, s, j);
            int dj = __shfl_sync(0xffffffffu, d, j);
            float aj = __shfl_sync(0xffffffffu, a, j);

            float4 xv = x[(long long)sj * 32 + lane];
            float4 m;
            m.x = fmaxf(fmaf(aj, we4.x, xv.x + be4.x), 0.0f);
            m.y = fmaxf(fmaf(aj, we4.y, xv.y + be4.y), 0.0f);
            m.z = fmaxf(fmaf(aj, we4.z, xv.z + be4.z), 0.0f);
            m.w = fmaxf(fmaf(aj, we4.w, xv.w + be4.w), 0.0f);

            float* p = aggr + ((long long)dj * 128 + lane * 4);
            asm volatile("red.global.add.v4.f32 [%0], {%1, %2, %3, %4};"
                         :: "l"(p), "f"(m.x), "f"(m.y), "f"(m.z), "f"(m.w)
                         : "memory");
        }
    }
}

// ---------------------------------------------------------------------------
// C[M,128] = act(A[M,128] @ W[128,128] + bias), act = relu if RELU
// 128x128 block tile, BK=8, 256 threads, 8x8 per thread.
// ---------------------------------------------------------------------------
template <bool RELU>
__global__ void __launch_bounds__(256) gemm128(
    const float* __restrict__ A, const float* __restrict__ W,
    const float* __restrict__ bias, float* __restrict__ C, int M)
{
    __shared__ float As[8][128];   // transposed A tile: As[k][row]
    __shared__ float Bs[8][128];   // Bs[k][col]

    const int tid = threadIdx.x;
    const int r0 = blockIdx.x * 128;
    const int tx = tid & 15;       // 0..15 -> cols tx*8
    const int ty = tid >> 4;       // 0..15 -> rows ty*8

    const int arow = tid >> 1;
    const int ahalf = tid & 1;
    const int bk = tid >> 5;
    const int bc = (tid & 31) * 4;

    float acc[8][8];
#pragma unroll
    for (int i = 0; i < 8; i++)
#pragma unroll
        for (int j = 0; j < 8; j++) acc[i][j] = 0.0f;

    for (int kb = 0; kb < 128; kb += 8) {
        float4 av = make_float4(0.f, 0.f, 0.f, 0.f);
        int gr = r0 + arow;
        if (gr < M) av = *(const float4*)(A + (long long)gr * 128 + kb + ahalf * 4);
        As[ahalf * 4 + 0][arow] = av.x;
        As[ahalf * 4 + 1][arow] = av.y;
        As[ahalf * 4 + 2][arow] = av.z;
        As[ahalf * 4 + 3][arow] = av.w;

        float4 bv = *(const float4*)(W + (kb + bk) * 128 + bc);
        *(float4*)(&Bs[bk][bc]) = bv;

        __syncthreads();

#pragma unroll
        for (int k = 0; k < 8; k++) {
            float4 a0 = *(const float4*)(&As[k][ty * 8]);
            float4 a1 = *(const float4*)(&As[k][ty * 8 + 4]);
            float4 b0 = *(const float4*)(&Bs[k][tx * 8]);
            float4 b1 = *(const float4*)(&Bs[k][tx * 8 + 4]);
            float ra[8] = {a0.x, a0.y, a0.z, a0.w, a1.x, a1.y, a1.z, a1.w};
            float rb[8] = {b0.x, b0.y, b0.z, b0.w, b1.x, b1.y, b1.z, b1.w};
#pragma unroll
            for (int i = 0; i < 8; i++)
#pragma unroll
                for (int j = 0; j < 8; j++)
                    acc[i][j] = fmaf(ra[i], rb[j], acc[i][j]);
        }
        __syncthreads();
    }

    float4 bv0 = *(const float4*)(bias + tx * 8);
    float4 bv1 = *(const float4*)(bias + tx * 8 + 4);
    float bb[8] = {bv0.x, bv0.y, bv0.z, bv0.w, bv1.x, bv1.y, bv1.z, bv1.w};

#pragma unroll
    for (int i = 0; i < 8; i++) {
        int gr = r0 + ty * 8 + i;
        if (gr >= M) continue;
#pragma unroll
        for (int j = 0; j < 8; j += 4) {
            float4 o;
            o.x = acc[i][j + 0] + bb[j + 0];
            o.y = acc[i][j + 1] + bb[j + 1];
            o.z = acc[i][j + 2] + bb[j + 2];
            o.w = acc[i][j + 3] + bb[j + 3];
            if (RELU) {
                o.x = fmaxf(o.x, 0.f); o.y = fmaxf(o.y, 0.f);
                o.z = fmaxf(o.z, 0.f); o.w = fmaxf(o.w, 0.f);
            }
            *(float4*)(C + (long long)gr * 128 + tx * 8 + j) = o;
        }
    }
}

// ---------------------------------------------------------------------------
// out[n, :] = log_softmax(H[n, :] @ Wl + bl)   H:[N,128], Wl:[128,40]
// 32 rows per block, 256 threads.
// ---------------------------------------------------------------------------
__global__ void __launch_bounds__(256) classify_lsm(
    const float* __restrict__ H, const float* __restrict__ Wl,
    const float* __restrict__ bl, float* __restrict__ out, int M)
{
    __shared__ float sW[128 * NC];
    __shared__ float sb[NC];
    __shared__ float sh[32 * 129];   // stride 129: kill bank conflicts
    __shared__ float sl[32 * NC];

    const int tid = threadIdx.x;
    const int r0 = blockIdx.x * 32;

    for (int i = tid; i < 128 * NC; i += 256) sW[i] = Wl[i];
    if (tid < NC) sb[tid] = bl[tid];
    for (int i = tid; i < 32 * 128; i += 256) {
        int row = i >> 7, col = i & 127;
        int gr = r0 + row;
        sh[row * 129 + col] = (gr < M) ? H[(long long)gr * 128 + col] : 0.0f;
    }
    __syncthreads();

#pragma unroll
    for (int t = 0; t < 5; t++) {
        int idx = tid + t * 256;               // < 1280 = 32*40
        int row = idx / NC, col = idx % NC;
        float acc = sb[col];
#pragma unroll 8
        for (int k = 0; k < 128; k++)
            acc = fmaf(sh[row * 129 + k], sW[k * NC + col], acc);
        sl[row * NC + col] = acc;
    }
    __syncthreads();

    if (tid < 32) {
        int row = tid;
        int gr = r0 + row;
        if (gr < M) {
            float mx = -1e30f;
            for (int c = 0; c < NC; c++) mx = fmaxf(mx, sl[row * NC + c]);
            float sum = 0.0f;
            for (int c = 0; c < NC; c++) sum += expf(sl[row * NC + c] - mx);
            float lse = mx + logf(sum);
            for (int c = 0; c < NC; c++)
                out[(long long)gr * NC + c] = sl[row * NC + c] - lse;
        }
    }
}

// ---------------------------------------------------------------------------
extern "C" void kernel_launch(void* const* d_in, const int* in_sizes, int n_in,
                              void* d_out, int out_size)
{
    const float* x    = (const float*)d_in[0];
    const int*   ei   = (const int*)d_in[1];      // int32! (JAX x64 disabled)
    const float* ea   = (const float*)d_in[2];
    const float* eps1 = (const float*)d_in[3];
    const float* We1  = (const float*)d_in[4];
    const float* be1  = (const float*)d_in[5];
    const float* W11  = (const float*)d_in[6];
    const float* b11  = (const float*)d_in[7];
    const float* W12  = (const float*)d_in[8];
    const float* b12  = (const float*)d_in[9];
    const float* eps2 = (const float*)d_in[10];
    const float* We2  = (const float*)d_in[11];
    const float* be2  = (const float*)d_in[12];
    const float* W21  = (const float*)d_in[13];
    const float* b21  = (const float*)d_in[14];
    const float* W22  = (const float*)d_in[15];
    const float* b22  = (const float*)d_in[16];
    const float* Wl   = (const float*)d_in[17];
    const float* bl   = (const float*)d_in[18];
    float* out = (float*)d_out;

    const int N = NN;
    const int E = in_sizes[2];   // edge_attr element count = E

    float *A, *B, *C;
    cudaGetSymbolAddress((void**)&A, g_bufA);
    cudaGetSymbolAddress((void**)&B, g_bufB);
    cudaGetSymbolAddress((void**)&C, g_bufC);

    const int n4 = N * FF / 4;                 // 3.2M float4
    const int scale_blocks = (n4 + 255) / 256;
    const int edge_blocks = ( (E + 31) / 32 + 7 ) / 8;   // 1 warp per 32-edge chunk
    const int gemm_blocks = (N + 127) / 128;
    const int cls_blocks = (N + 31) / 32;

    // ---- Layer 1 ----
    scale_copy<<<scale_blocks, 256>>>((const float4*)x, eps1, (float4*)A, n4);
    edge_msg<<<edge_blocks, 256>>>((const float4*)x, ei, ea, We1, be1, A, E);
    gemm128<true><<<gemm_blocks, 256>>>(A, W11, b11, B, N);
    gemm128<true><<<gemm_blocks, 256>>>(B, W12, b12, C, N);   // includes outer relu

    // ---- Layer 2 ----
    scale_copy<<<scale_blocks, 256>>>((const float4*)C, eps2, (float4*)B, n4);
    edge_msg<<<edge_blocks, 256>>>((const float4*)C, ei, ea, We2, be2, B, E);
    gemm128<true><<<gemm_blocks, 256>>>(B, W21, b21, A, N);
    gemm128<true><<<gemm_blocks, 256>>>(A, W22, b22, B, N);   // includes outer relu

    // ---- Classifier + log_softmax ----
    classify_lsm<<<cls_blocks, 256>>>(B, Wl, bl, out, N);
}